// round 5
// baseline (speedup 1.0000x reference)
#include <cuda_runtime.h>
#include <cuda_bf16.h>
#include <stdint.h>

#define L 4096

// Fused single kernel. Grid = 16384 blocks; block b handles TWO consecutive
// rows of one channel:  c = b >> 11 (0..7),  i0 = (b & 2047) * 2.
//   c in [0,4): row r = broadcast of (seq[i]==c)  — 2 id loads, 8x STG.128
//   c in [4,8): rows are IDENTICAL (depend only on j): compute 4 one-hot quads
//               once, store each to both rows — 8x STG.128.
//
// int64-vs-int32 detection (sync-free, warp-uniform): for int64 ids in [0,3],
// every odd 32-bit word is 0. OR the odd words of the first 128 bytes
// (8 broadcast LDG.128, MLP=8). acc==0 <=> int64; false-positive prob for
// random int32 ids = 4^-16 ~ 2^-32 (and deterministic given the fixed seed).
__global__ void __launch_bounds__(256) seq_embed_fused2_kernel(
        const int* __restrict__ raw, float4* __restrict__ out) {
    const int4* p4 = reinterpret_cast<const int4*>(raw);

    int acc = 0;
    #pragma unroll
    for (int k = 0; k < 8; k++) {
        int4 w = p4[k];
        acc |= w.y | w.w;          // odd 32-bit words
    }
    const bool is64 = (acc == 0);

    unsigned int b  = blockIdx.x;
    unsigned int c  = b >> 11;            // channel 0..7
    unsigned int i0 = (b & 2047u) << 1;   // first of two rows
    unsigned int tx = threadIdx.x;

    // row pointers: global row r = c*4096 + i, each row = 1024 float4 (16 KB)
    float4* row0 = out + ((size_t)(c * 4096u + i0)) * 1024u;
    float4* row1 = row0 + 1024u;

    if (c < 4u) {
        int v0, v1;
        if (is64) {
            const long long* p64 = reinterpret_cast<const long long*>(raw);
            v0 = (int)p64[i0];
            v1 = (int)p64[i0 + 1];
        } else {
            v0 = raw[i0];
            v1 = raw[i0 + 1];
        }
        float x0 = (v0 == (int)c) ? 1.0f : 0.0f;
        float x1 = (v1 == (int)c) ? 1.0f : 0.0f;
        float4 a0 = {x0, x0, x0, x0};
        float4 a1 = {x1, x1, x1, x1};
        #pragma unroll
        for (int k = 0; k < 4; k++) {
            __stcs(row0 + tx + k * 256u, a0);
            __stcs(row1 + tx + k * 256u, a1);
        }
    } else {
        int cc = (int)c - 4;
        #pragma unroll
        for (int k = 0; k < 4; k++) {
            unsigned int j4 = tx + k * 256u;   // quad index: ids 4*j4..4*j4+3
            int v0, v1, v2, v3;
            if (is64) {
                int4 a = p4[2 * j4];
                int4 d = p4[2 * j4 + 1];
                v0 = a.x; v1 = a.z; v2 = d.x; v3 = d.z;
            } else {
                int4 a = p4[j4];
                v0 = a.x; v1 = a.y; v2 = a.z; v3 = a.w;
            }
            float4 v;
            v.x = (v0 == cc) ? 1.0f : 0.0f;
            v.y = (v1 == cc) ? 1.0f : 0.0f;
            v.z = (v2 == cc) ? 1.0f : 0.0f;
            v.w = (v3 == cc) ? 1.0f : 0.0f;
            __stcs(row0 + j4, v);
            __stcs(row1 + j4, v);   // identical row content for c in [4,8)
        }
    }
}

extern "C" void kernel_launch(void* const* d_in, const int* in_sizes, int n_in,
                              void* d_out, int out_size) {
    const int* raw_seq = (const int*)d_in[0];   // seq_ids (int64 or int32, auto-detected)
    // d_in[1] is base_table (identity eye(4)) — comparisons suffice.

    // 8 channels * 2048 row-pairs = 16384 blocks, 32 KB written per block.
    seq_embed_fused2_kernel<<<16384, 256>>>(raw_seq, (float4*)d_out);
}

// round 7
// speedup vs baseline: 1.0190x; 1.0190x over previous
#include <cuda_runtime.h>
#include <cuda_bf16.h>
#include <stdint.h>

#define L 4096

// Fused single kernel, R2 store structure: one block per output row (c, i).
// Grid = 32768:  c = b >> 12 (channel 0..7), i = b & 4095.
//   c in [0,4): row = broadcast of (seq[i]==c)   — 1 id load, 4x STG.128
//   c in [4,8): row = one-hot of seq[j] vs (c-4) — 4x (id load + cmp + STG.128)
// One 16 KB contiguous row per block keeps DRAM write-page locality maximal
// (R4's 2-rows-per-block variant measured 2.5% worse DRAM utilization).
//
// int64-vs-int32 detection (sync-free, warp-uniform): for int64 ids in [0,3],
// every odd 32-bit word is 0. OR the odd words of the first 128 bytes
// (8 broadcast LDG.128, MLP=8, L2-resident). acc==0 <=> int64;
// false-positive prob for int32 ids ~ 4^-16 ~ 2^-32.
__global__ void __launch_bounds__(256) seq_embed_fused_row_kernel(
        const int* __restrict__ raw, float4* __restrict__ out) {
    const int4* p4 = reinterpret_cast<const int4*>(raw);

    int acc = 0;
    #pragma unroll
    for (int k = 0; k < 8; k++) {
        int4 w = p4[k];
        acc |= w.y | w.w;          // odd 32-bit words
    }
    const bool is64 = (acc == 0);

    unsigned int b  = blockIdx.x;
    unsigned int c  = b >> 12;        // channel 0..7
    unsigned int i  = b & 4095u;      // row index
    unsigned int tx = threadIdx.x;

    float4* rowp = out + (size_t)b * 1024u;   // 1024 float4 = 16 KB per row

    if (c < 4u) {
        int vi = is64 ? (int)reinterpret_cast<const long long*>(raw)[i]
                      : raw[i];
        float x = (vi == (int)c) ? 1.0f : 0.0f;
        float4 v = {x, x, x, x};
        #pragma unroll
        for (int k = 0; k < 4; k++)
            __stcs(rowp + tx + k * 256u, v);
    } else {
        int cc = (int)c - 4;
        #pragma unroll
        for (int k = 0; k < 4; k++) {
            unsigned int j4 = tx + k * 256u;   // quad index: ids 4*j4..4*j4+3
            int v0, v1, v2, v3;
            if (is64) {
                int4 a = p4[2 * j4];
                int4 d = p4[2 * j4 + 1];
                v0 = a.x; v1 = a.z; v2 = d.x; v3 = d.z;
            } else {
                int4 a = p4[j4];
                v0 = a.x; v1 = a.y; v2 = a.z; v3 = a.w;
            }
            float4 v;
            v.x = (v0 == cc) ? 1.0f : 0.0f;
            v.y = (v1 == cc) ? 1.0f : 0.0f;
            v.z = (v2 == cc) ? 1.0f : 0.0f;
            v.w = (v3 == cc) ? 1.0f : 0.0f;
            __stcs(rowp + j4, v);
        }
    }
}

extern "C" void kernel_launch(void* const* d_in, const int* in_sizes, int n_in,
                              void* d_out, int out_size) {
    const int* raw_seq = (const int*)d_in[0];   // seq_ids (int64 or int32, auto-detected)
    // d_in[1] is base_table (identity eye(4)) — comparisons suffice.

    // 8 channels * 4096 rows = 32768 blocks, one 16 KB row each.
    seq_embed_fused_row_kernel<<<8 * L, 256>>>(raw_seq, (float4*)d_out);
}